// round 2
// baseline (speedup 1.0000x reference)
#include <cuda_runtime.h>

#define DT 0.01f

constexpr int B   = 2;
constexpr int N   = 20000;
constexpr int D   = 64;
constexpr int E   = 320000;
constexpr int ND4 = N * (D / 4);   // float4s per batch  = 320000
constexpr int TOT4 = B * ND4;      // total float4s      = 640000

// Scratch (allocation-free rule: __device__ globals).
// float4 type guarantees the 16B alignment red.global.add.v4.f32 requires.
__device__ float4 g_acc[TOT4];     // sum of q[src] scattered to dst, per batch
__device__ int    g_deg[N];        // in-degree per node (shared across batch)

__device__ __forceinline__ void red4(float4* p, float4 v) {
    asm volatile("red.global.add.v4.f32 [%0], {%1, %2, %3, %4};"
                 :: "l"(p), "f"(v.x), "f"(v.y), "f"(v.z), "f"(v.w)
                 : "memory");
}

__global__ void zero_kernel() {
    int i = blockIdx.x * blockDim.x + threadIdx.x;
    if (i < TOT4) g_acc[i] = make_float4(0.f, 0.f, 0.f, 0.f);
    if (i < N)    g_deg[i] = 0;
}

// 16 threads per edge; each thread handles one float4 chunk of D for BOTH batches.
// Only ONE gather per edge (q[src]) — the q[dst] term is folded into the
// epilogue as deg[n]*q[n].
__global__ void edge_kernel(const int2* __restrict__ edges, const float* __restrict__ q) {
    int gid  = blockIdx.x * blockDim.x + threadIdx.x;
    int e    = gid >> 4;
    if (e >= E) return;
    int lane = gid & 15;

    int2 ed = __ldg(&edges[e]);
    int src = ed.x;
    int dst = ed.y;

    const float4* q4 = reinterpret_cast<const float4*>(q);

    // batch 0
    float4 v0 = q4[src * 16 + lane];
    red4(g_acc + dst * 16 + lane, v0);
    // batch 1
    float4 v1 = q4[ND4 + src * 16 + lane];
    red4(g_acc + ND4 + dst * 16 + lane, v1);

    if (lane == 0) atomicAdd(&g_deg[dst], 1);
}

// Fused epilogue: msg = deg*q - acc; symplectic update; Kalman correction on node 0.
__global__ void finalize_kernel(const float* __restrict__ q, const float* __restrict__ p,
                                const float* __restrict__ obs, const float* __restrict__ kg,
                                float* __restrict__ out) {
    int gid = blockIdx.x * blockDim.x + threadIdx.x;
    if (gid >= TOT4) return;

    int c = gid & 15;            // float4 chunk within D
    int n = (gid >> 4) % N;      // node
    int b = gid / ND4;           // batch

    const float4* q4 = reinterpret_cast<const float4*>(q);
    const float4* p4 = reinterpret_cast<const float4*>(p);

    float4 qq = q4[gid];
    float4 pp = p4[gid];
    float4 aa = g_acc[gid];
    float  dg = (float)g_deg[n];

    // msg = deg * q - sum(q[src])
    float mx = dg * qq.x - aa.x;
    float my = dg * qq.y - aa.y;
    float mz = dg * qq.z - aa.z;
    float mw = dg * qq.w - aa.w;

    // p_half = p + 0.5*DT*msg ; q_new = q + DT*p_half ; p_new = p + DT*msg
    float phx = pp.x + 0.5f * DT * mx;
    float phy = pp.y + 0.5f * DT * my;
    float phz = pp.z + 0.5f * DT * mz;
    float phw = pp.w + 0.5f * DT * mw;

    float qnx = qq.x + DT * phx;
    float qny = qq.y + DT * phy;
    float qnz = qq.z + DT * phz;
    float qnw = qq.w + DT * phw;

    float pnx = pp.x + DT * mx;
    float pny = pp.y + DT * my;
    float pnz = pp.z + DT * mz;
    float pnw = pp.w + DT * mw;

    if (n == 0) {
        const float4* obs4 = reinterpret_cast<const float4*>(obs);
        const float4* kg4  = reinterpret_cast<const float4*>(kg);
        float4 ob = obs4[b * 16 + c];
        float4 kq = kg4[c];        // kalman_gain[0:D]
        float4 kp = kg4[16 + c];   // kalman_gain[D:2D]

        float ix = ob.x - qnx, iy = ob.y - qny, iz = ob.z - qnz, iw = ob.w - qnw;
        qnx += kq.x * ix;  qny += kq.y * iy;  qnz += kq.z * iz;  qnw += kq.w * iw;
        pnx += kp.x * ix;  pny += kp.y * iy;  pnz += kp.z * iz;  pnw += kp.w * iw;
    }

    float4* o4 = reinterpret_cast<float4*>(out);
    o4[gid]        = make_float4(qnx, qny, qnz, qnw);   // q_new
    o4[TOT4 + gid] = make_float4(pnx, pny, pnz, pnw);   // p_new
}

extern "C" void kernel_launch(void* const* d_in, const int* in_sizes, int n_in,
                              void* d_out, int out_size) {
    const float* q    = (const float*)d_in[0];   // node_q  (B,N,D) f32
    const float* p    = (const float*)d_in[1];   // node_p  (B,N,D) f32
    const float* obs  = (const float*)d_in[2];   // observations (B,D) f32
    const float* kg   = (const float*)d_in[3];   // kalman_gain (2D,) f32
    const int2*  edg  = (const int2*)d_in[4];    // edges (E,2) i32
    float* out = (float*)d_out;

    zero_kernel<<<(TOT4 + 255) / 256, 256>>>();
    edge_kernel<<<(E * 16 + 255) / 256, 256>>>(edg, q);
    finalize_kernel<<<(TOT4 + 255) / 256, 256>>>(q, p, obs, kg, out);
}